// round 2
// baseline (speedup 1.0000x reference)
#include <cuda_runtime.h>
#include <cstddef>

// Sparsemax (alpha=2) via candidate-set reduction.
// Row lives in registers: 800 threads x 10 float4 = 32000 floats exactly.
// tau computed in closed form (sorted-threshold sparsemax rule) over the tiny
// candidate set {x : x > rowmax - 1}; every bisection iterate of the reference
// lies above rowmax-1, so all other elements contribute 0 to f(tau).
// Closed-form tau == bisection limit within fp32 rounding (bisection converges
// to 2^-50), so outputs agree to ~1e-6 rel.

#define SPM_D   32000
#define SPM_NT  800
#define SPM_NW  (SPM_NT / 32)   // 25 warps
#define SPM_NV  10              // float4 per thread: 800*10*4 = 32000
#define SPM_CAP 2048

#define NEG_INF (-3.402823466e38f)
#define FULLMASK 0xffffffffu

__device__ int g_row_counter;

__global__ void spm_reset_kernel() { g_row_counter = 0; }

__device__ __forceinline__ float warp_max(float v) {
#pragma unroll
    for (int o = 16; o; o >>= 1) v = fmaxf(v, __shfl_xor_sync(FULLMASK, v, o));
    return v;
}
__device__ __forceinline__ float warp_sum(float v) {
#pragma unroll
    for (int o = 16; o; o >>= 1) v += __shfl_xor_sync(FULLMASK, v, o);
    return v;
}

__global__ __launch_bounds__(SPM_NT, 1)
void spm_kernel(const float* __restrict__ X, float* __restrict__ Y, int rows) {
    __shared__ float s_red[SPM_NW];
    __shared__ float s_cand[SPM_CAP];
    __shared__ int   s_cnt;
    __shared__ int   s_row;

    const int tid  = threadIdx.x;
    const int lane = tid & 31;
    const int wid  = tid >> 5;
    const float inv_d = 1.0f / (float)SPM_D;

    for (;;) {
        if (tid == 0) {
            s_row = atomicAdd(&g_row_counter, 1);
            s_cnt = 0;
        }
        __syncthreads();                 // row fetch + orders s_cnt reset
        const int row = s_row;
        if (row >= rows) break;

        const float4* __restrict__ x4 =
            reinterpret_cast<const float4*>(X + (size_t)row * (size_t)SPM_D);
        float4* __restrict__ y4 =
            reinterpret_cast<float4*>(Y + (size_t)row * (size_t)SPM_D);

        // ---- Load row into registers + per-thread max ----
        float4 v[SPM_NV];
        float mx = NEG_INF;
#pragma unroll
        for (int j = 0; j < SPM_NV; ++j) {
            v[j] = __ldcs(&x4[j * SPM_NT + tid]);
            mx = fmaxf(mx, fmaxf(fmaxf(v[j].x, v[j].y), fmaxf(v[j].z, v[j].w)));
        }
        mx = warp_max(mx);
        if (lane == 0) s_red[wid] = mx;
        __syncthreads();

        // every warp redundantly reduces the 25 partials (no 2nd barrier)
        float m = (lane < SPM_NW) ? s_red[lane] : NEG_INF;
        const float mxv = warp_max(m);
        const float thr = mxv - 1.0f;

        // ---- Gather candidates (> max-1) into smem ----
#pragma unroll
        for (int j = 0; j < SPM_NV; ++j) {
            float c;
            c = v[j].x; if (c > thr) { int p = atomicAdd(&s_cnt, 1); if (p < SPM_CAP) s_cand[p] = c; }
            c = v[j].y; if (c > thr) { int p = atomicAdd(&s_cnt, 1); if (p < SPM_CAP) s_cand[p] = c; }
            c = v[j].z; if (c > thr) { int p = atomicAdd(&s_cnt, 1); if (p < SPM_CAP) s_cand[p] = c; }
            c = v[j].w; if (c > thr) { int p = atomicAdd(&s_cnt, 1); if (p < SPM_CAP) s_cand[p] = c; }
        }
        __syncthreads();
        const int K = s_cnt;

        float tau, inv;

        if (K <= 32) {
            // ---- Closed-form sparsemax threshold, per-warp (redundant) ----
            float z = (lane < K) ? s_cand[lane] : NEG_INF;

            // bitonic sort, descending
#pragma unroll
            for (int k = 2; k <= 32; k <<= 1) {
#pragma unroll
                for (int j = k >> 1; j > 0; j >>= 1) {
                    float o = __shfl_xor_sync(FULLMASK, z, j);
                    bool lower   = (lane & j) == 0;
                    bool descBlk = (lane & k) == 0;
                    z = (lower == descBlk) ? fmaxf(z, o) : fminf(z, o);
                }
            }
            // inclusive prefix sum
            float S = z;
#pragma unroll
            for (int o = 1; o < 32; o <<= 1) {
                float t = __shfl_up_sync(FULLMASK, S, o);
                if (lane >= o) S += t;
            }
            // support rule: k = max{ i+1 : 1 + (i+1) z_i > S_{i+1} }
            float kk = (float)(lane + 1);
            unsigned bal = __ballot_sync(FULLMASK, fmaf(kk, z, 1.0f) > S);
            int h = 31 - __clz(bal);    // bal != 0: lane 0 always qualifies
            tau = __shfl_sync(FULLMASK, (S - 1.0f) / kk, h);
            float s = warp_sum(fmaxf(z - tau, 0.0f));
            inv = 1.0f / s;
        } else if (K <= SPM_CAP) {
            // ---- Exact reference bisection over candidates, per-warp ----
            float tlo = thr;
            float dm  = (mxv - inv_d) - tlo;
            float a = 0.0f;
            for (int i = lane; i < K; i += 32) a += fmaxf(s_cand[i] - tlo, 0.0f);
            const float flo = warp_sum(a) - 1.0f;
            float tm = tlo, fm = flo;
            for (int it = 0; it < 50; ++it) {
                dm *= 0.5f;
                tm = tlo + dm;
                float s = 0.0f;
                for (int i = lane; i < K; i += 32) s += fmaxf(s_cand[i] - tm, 0.0f);
                fm = warp_sum(s) - 1.0f;
                if (fm * flo >= 0.0f) tlo = tm;
            }
            tau = tm;
            inv = 1.0f / (fm + 1.0f);
        } else {
            // ---- Overflow fallback: block bisection over register row ----
            float tlo = thr;
            float dm  = (mxv - inv_d) - tlo;

            float a = 0.0f;
#pragma unroll
            for (int j = 0; j < SPM_NV; ++j)
                a += fmaxf(v[j].x - tlo, 0.0f) + fmaxf(v[j].y - tlo, 0.0f) +
                     fmaxf(v[j].z - tlo, 0.0f) + fmaxf(v[j].w - tlo, 0.0f);
            a = warp_sum(a);
            __syncthreads();
            if (lane == 0) s_red[wid] = a;
            __syncthreads();
            float r0 = (lane < SPM_NW) ? s_red[lane] : 0.0f;
            const float flo = warp_sum(r0) - 1.0f;

            float tm = tlo, fm = flo;
            for (int it = 0; it < 50; ++it) {
                dm *= 0.5f;
                tm = tlo + dm;
                float s = 0.0f;
#pragma unroll
                for (int j = 0; j < SPM_NV; ++j)
                    s += fmaxf(v[j].x - tm, 0.0f) + fmaxf(v[j].y - tm, 0.0f) +
                         fmaxf(v[j].z - tm, 0.0f) + fmaxf(v[j].w - tm, 0.0f);
                s = warp_sum(s);
                __syncthreads();
                if (lane == 0) s_red[wid] = s;
                __syncthreads();
                float rr = (lane < SPM_NW) ? s_red[lane] : 0.0f;
                fm = warp_sum(rr) - 1.0f;
                if (fm * flo >= 0.0f) tlo = tm;
            }
            tau = tm;
            inv = 1.0f / (fm + 1.0f);
        }

        // ---- Write p = max(x - tau, 0) * inv (streaming stores) ----
#pragma unroll
        for (int j = 0; j < SPM_NV; ++j) {
            float4 r;
            r.x = fmaxf(v[j].x - tau, 0.0f) * inv;
            r.y = fmaxf(v[j].y - tau, 0.0f) * inv;
            r.z = fmaxf(v[j].z - tau, 0.0f) * inv;
            r.w = fmaxf(v[j].w - tau, 0.0f) * inv;
            __stcs(&y4[j * SPM_NT + tid], r);
        }
    }
}

extern "C" void kernel_launch(void* const* d_in, const int* in_sizes, int n_in,
                              void* d_out, int out_size) {
    const float* X = (const float*)d_in[0];
    float* Y       = (float*)d_out;
    const int rows = in_sizes[0] / SPM_D;

    int dev = 0;
    cudaGetDevice(&dev);
    int sms = 148;
    cudaDeviceGetAttribute(&sms, cudaDevAttrMultiProcessorCount, dev);

    spm_reset_kernel<<<1, 1>>>();
    spm_kernel<<<sms, SPM_NT>>>(X, Y, rows);
}

// round 3
// speedup vs baseline: 1.4460x; 1.4460x over previous
#include <cuda_runtime.h>
#include <cstddef>

// Sparsemax (alpha=2). Single-read gather: while streaming the row (DRAM),
// each warp collects values > (running warp max - 1) -- a superset of the
// true candidate set {x : x > rowmax-1}, since the running max only grows.
// After the block max is known, the superset is filtered and tau computed in
// closed form (sorted-threshold rule) for K<=32 (typical K ~ 8-30 for this
// data), warp bisection for larger K, full-row block bisection as the
// correctness fallback. Then one L2-resident re-read produces the output.

#define SPM_D   32000
#define SPM_D4  (SPM_D / 4)      // 8000 float4
#define SPM_NT  512
#define SPM_NW  (SPM_NT / 32)    // 16 warps
#define WBUF    256              // per-warp superset buffer
#define FCAP    512              // filtered candidate cap

#define NEG_INF (-3.402823466e38f)
#define FULL    0xffffffffu

__device__ __forceinline__ float warp_max(float v) {
#pragma unroll
    for (int o = 16; o; o >>= 1) v = fmaxf(v, __shfl_xor_sync(FULL, v, o));
    return v;
}
__device__ __forceinline__ float warp_sum(float v) {
#pragma unroll
    for (int o = 16; o; o >>= 1) v += __shfl_xor_sync(FULL, v, o);
    return v;
}

__global__ __launch_bounds__(SPM_NT, 3)
void spm_kernel(const float* __restrict__ X, float* __restrict__ Y) {
    __shared__ float s_buf[SPM_NW][WBUF];
    __shared__ float s_filt[FCAP];
    __shared__ float s_wmax[SPM_NW];
    __shared__ int   s_cnt[SPM_NW];
    __shared__ float s_r[SPM_NW];
    __shared__ int   s_K, s_flag;
    __shared__ float s_tau, s_inv, s_f;

    const int tid  = threadIdx.x;
    const int lane = tid & 31;
    const int wid  = tid >> 5;
    const unsigned ltmask = (1u << lane) - 1u;
    const int row = blockIdx.x;

    const float4* __restrict__ x4 =
        reinterpret_cast<const float4*>(X + (size_t)row * (size_t)SPM_D);
    float4* __restrict__ y4 =
        reinterpret_cast<float4*>(Y + (size_t)row * (size_t)SPM_D);

    if (tid == 0) { s_K = 0; s_flag = 0; }

    // ---- Pass 1: stream row (DRAM), running-max superset gather ----
    float wmax = NEG_INF;
    int   cnt  = 0;
    float thr  = NEG_INF;

#define SPM_GATHER(c)                                                          \
    {                                                                          \
        bool q = (c) > thr;                                                    \
        unsigned b = __ballot_sync(FULL, q);                                   \
        if (q) {                                                               \
            int p = cnt + __popc(b & ltmask);                                  \
            if (p < WBUF) s_buf[wid][p] = (c);                                 \
        }                                                                      \
        cnt += __popc(b);                                                      \
    }

    for (int i = tid; i < SPM_D4; i += 2 * SPM_NT) {
        float4 v0 = x4[i];
        bool have1 = (i + SPM_NT) < SPM_D4;   // uniform per warp (8000 % 32 == 0)
        float4 v1;
        if (have1) v1 = x4[i + SPM_NT];

        float m8 = fmaxf(fmaxf(v0.x, v0.y), fmaxf(v0.z, v0.w));
        if (have1)
            m8 = fmaxf(m8, fmaxf(fmaxf(v1.x, v1.y), fmaxf(v1.z, v1.w)));
        wmax = fmaxf(wmax, warp_max(m8));
        thr  = wmax - 1.0f;

        SPM_GATHER(v0.x); SPM_GATHER(v0.y); SPM_GATHER(v0.z); SPM_GATHER(v0.w);
        if (have1) {
            SPM_GATHER(v1.x); SPM_GATHER(v1.y); SPM_GATHER(v1.z); SPM_GATHER(v1.w);
        }
    }
#undef SPM_GATHER

    if (lane == 0) {
        s_wmax[wid] = wmax;
        s_cnt[wid]  = cnt;
        if (cnt > WBUF) s_flag = 1;
    }
    __syncthreads();

    float m = (lane < SPM_NW) ? s_wmax[lane] : NEG_INF;
    const float mxv  = warp_max(m);           // block max, all warps redundantly
    const float thrF = mxv - 1.0f;
    const float inv_d = 1.0f / (float)SPM_D;

    bool need_full = (s_flag != 0);
    float tau = 0.0f, inv = 1.0f;

    if (!need_full) {
        // ---- Filter superset -> true candidates (> rowmax - 1) ----
        const int c = s_cnt[wid];
        for (int i = lane; i < c; i += 32) {
            float val = s_buf[wid][i];
            if (val > thrF) {
                int p = atomicAdd(&s_K, 1);
                if (p < FCAP) s_filt[p] = val;
            }
        }
        __syncthreads();
        const int K = s_K;   // uniform

        if (K >= 1 && K <= 32) {
            // ---- Closed-form threshold, redundantly per-warp (no barrier) ----
            float z = (lane < K) ? s_filt[lane] : NEG_INF;
            // bitonic sort, descending
#pragma unroll
            for (int k = 2; k <= 32; k <<= 1) {
#pragma unroll
                for (int j = k >> 1; j > 0; j >>= 1) {
                    float o = __shfl_xor_sync(FULL, z, j);
                    bool lower   = (lane & j) == 0;
                    bool descBlk = (lane & k) == 0;
                    z = (lower == descBlk) ? fmaxf(z, o) : fminf(z, o);
                }
            }
            // inclusive prefix sum
            float S = z;
#pragma unroll
            for (int o = 1; o < 32; o <<= 1) {
                float t = __shfl_up_sync(FULL, S, o);
                if (lane >= o) S += t;
            }
            float kk = (float)(lane + 1);
            unsigned bal = __ballot_sync(FULL, fmaf(kk, z, 1.0f) > S);
            int h = 31 - __clz(bal);          // lane 0 always qualifies
            tau = __shfl_sync(FULL, (S - 1.0f) / kk, h);
            float s = warp_sum(fmaxf(z - tau, 0.0f));
            inv = 1.0f / s;
        } else if (K <= FCAP) {
            // ---- Reference bisection over candidates (warp 0) ----
            if (wid == 0) {
                float tlo = thrF;
                float dm  = (mxv - inv_d) - tlo;
                float a = 0.0f;
                for (int i = lane; i < K; i += 32)
                    a += fmaxf(s_filt[i] - tlo, 0.0f);
                const float flo = warp_sum(a) - 1.0f;
                float tm = tlo, fm = flo;
                for (int it = 0; it < 50; ++it) {
                    dm *= 0.5f;
                    tm = tlo + dm;
                    float s = 0.0f;
                    for (int i = lane; i < K; i += 32)
                        s += fmaxf(s_filt[i] - tm, 0.0f);
                    fm = warp_sum(s) - 1.0f;
                    if (fm * flo >= 0.0f) tlo = tm;
                }
                if (lane == 0) { s_tau = tm; s_inv = 1.0f / (fm + 1.0f); }
            }
            __syncthreads();
            tau = s_tau; inv = s_inv;
        } else {
            need_full = true;  // uniform
        }
    }

    if (need_full) {
        // ---- Correctness fallback: block bisection over full row (L2) ----
        float tlo = thrF;
        float dm  = (mxv - inv_d) - tlo;

        float a = 0.0f;
        for (int i = tid; i < SPM_D4; i += SPM_NT) {
            float4 v = x4[i];
            a += fmaxf(v.x - tlo, 0.0f) + fmaxf(v.y - tlo, 0.0f) +
                 fmaxf(v.z - tlo, 0.0f) + fmaxf(v.w - tlo, 0.0f);
        }
        a = warp_sum(a);
        if (lane == 0) s_r[wid] = a;
        __syncthreads();
        float r0 = (lane < SPM_NW) ? s_r[lane] : 0.0f;
        const float flo = warp_sum(r0) - 1.0f;

        float tm = tlo, fm = flo;
        for (int it = 0; it < 50; ++it) {
            dm *= 0.5f;
            tm = tlo + dm;
            float s = 0.0f;
            for (int i = tid; i < SPM_D4; i += SPM_NT) {
                float4 v = x4[i];
                s += fmaxf(v.x - tm, 0.0f) + fmaxf(v.y - tm, 0.0f) +
                     fmaxf(v.z - tm, 0.0f) + fmaxf(v.w - tm, 0.0f);
            }
            s = warp_sum(s);
            __syncthreads();
            if (lane == 0) s_r[wid] = s;
            __syncthreads();
            float rr = (lane < SPM_NW) ? s_r[lane] : 0.0f;
            fm = warp_sum(rr) - 1.0f;
            if (fm * flo >= 0.0f) tlo = tm;
        }
        tau = tm;
        inv = 1.0f / (fm + 1.0f);
    }

    // ---- Pass 2: L2 re-read + streaming write ----
#pragma unroll 4
    for (int i = tid; i < SPM_D4; i += SPM_NT) {
        float4 v = __ldcg(&x4[i]);
        float4 r;
        r.x = fmaxf(v.x - tau, 0.0f) * inv;
        r.y = fmaxf(v.y - tau, 0.0f) * inv;
        r.z = fmaxf(v.z - tau, 0.0f) * inv;
        r.w = fmaxf(v.w - tau, 0.0f) * inv;
        __stcs(&y4[i], r);
    }
}

extern "C" void kernel_launch(void* const* d_in, const int* in_sizes, int n_in,
                              void* d_out, int out_size) {
    const float* X = (const float*)d_in[0];
    float* Y       = (float*)d_out;
    const int rows = in_sizes[0] / SPM_D;

    spm_kernel<<<rows, SPM_NT>>>(X, Y);
}